// round 14
// baseline (speedup 1.0000x reference)
#include <cuda_runtime.h>
#include <cuda_bf16.h>
#include <math.h>
#include <stdint.h>

#define BATCH 4096
#define TT    16
#define PP    10
#define PREV_ 5
typedef __nv_bfloat16 bf16;

// ================= device scratch =================
__device__ float g_c[BATCH * 256];
__device__ float g_lam[PP * BATCH];
__device__ float g_bg[1024];
__device__ float g_bq[256];
__device__ float g_bml[512];
__device__ bf16 g_hi_h[BATCH * 256],   g_hi_l[BATCH * 256];
__device__ bf16 g_z_h[2 * BATCH * 128], g_z_l[2 * BATCH * 128];
__device__ bf16 g_y_h[2 * BATCH * 256], g_y_l[2 * BATCH * 256];
__device__ bf16 g_h_h[2 * BATCH * 256], g_h_l[2 * BATCH * 256];
__device__ bf16 g_hraw_h[BATCH * 256], g_hraw_l[BATCH * 256];
__device__ bf16 g_y1_h[BATCH * 256],   g_y1_l[BATCH * 256];
__device__ bf16 g_y2_h[BATCH * 256],   g_y2_l[BATCH * 256];
__device__ bf16 g_HZ_h[BATCH * 256],   g_HZ_l[BATCH * 256];
// fragment-major weights (PTX m16n8k16 B-fragment layout, ks0/ks1 packed per 16B)
__device__ bf16 g_Wgt_h[1024 * 896],  g_Wgt_l[1024 * 896];   // gate-interleaved
__device__ bf16 g_W1t_h[256 * 256],   g_W1t_l[256 * 256];
__device__ bf16 g_W2t_h[256 * 256],   g_W2t_l[256 * 256];
__device__ bf16 g_W3t_h[256 * 256],   g_W3t_l[256 * 256];
__device__ bf16 g_Wqt_h[256 * 1024],  g_Wqt_l[256 * 1024];
__device__ bf16 g_Wmlt_h[512 * 256],  g_Wmlt_l[512 * 256];   // stat-interleaved

__device__ __forceinline__ void split_bf16(float x, bf16& h, bf16& l) {
    h = __float2bfloat16(x);
    l = __float2bfloat16(x - __bfloat162float(h));
}
__device__ __forceinline__ uint32_t s2u(const void* p) {
    uint32_t r;
    asm("{ .reg .u64 t; cvta.to.shared.u64 t, %1; cvt.u32.u64 %0, t; }"
        : "=r"(r) : "l"(p));
    return r;
}
__device__ __forceinline__ void cpa(uint32_t d, const void* s) {
    asm volatile("cp.async.cg.shared.global [%0], [%1], 16;" :: "r"(d), "l"(s));
}
__device__ __forceinline__ void ldm_x4(uint32_t& r0, uint32_t& r1,
                                       uint32_t& r2, uint32_t& r3, uint32_t a) {
    asm volatile("ldmatrix.sync.aligned.m8n8.x4.shared.b16 {%0,%1,%2,%3}, [%4];"
                 : "=r"(r0), "=r"(r1), "=r"(r2), "=r"(r3) : "r"(a));
}
__device__ __forceinline__ void mma16816(float* c, const uint32_t* a,
                                         const uint32_t* b) {
    asm volatile(
        "mma.sync.aligned.m16n8k16.row.col.f32.bf16.bf16.f32 "
        "{%0,%1,%2,%3}, {%4,%5,%6,%7}, {%8,%9}, {%0,%1,%2,%3};"
        : "+f"(c[0]), "+f"(c[1]), "+f"(c[2]), "+f"(c[3])
        : "r"(a[0]), "r"(a[1]), "r"(a[2]), "r"(a[3]), "r"(b[0]), "r"(b[1]));
}
__device__ __forceinline__ float sigm(float x) { return 1.f / (1.f + expf(-x)); }

// ================= HMMA bf16x3 GEMM, A via cp.async smem, B via fragment LDG ===
// BM=64, BN=128, BK=32, 3-stage A-only pipeline, 8 warps (2M x 4N).
// B fragments loaded per-ks as uint2 halves (16 fewer hot regs) so the gates
// kernel fits 3 CTAs/SM (MINB=3 -> 24 warps); small GEMMs stay MINB=2.
// GSEG: 0 single A src; 1 gates segs {128,256,256,256}; 2 xq segs {256 x4}.
// EPI:  0 bias/relu (+WBF, +WYS); 1 fused LSTM; 2 fused sampling.
#define NT   4
#define ASTG (64 * 80)             // 5120, one A array (h or l)
#define SSZ  (2 * ASTG)            // 10240 per stage
#define SMTOT (3 * SSZ)            // 30720

template<int GSEG, int EPI, int WBF, int WYS, int MINB>
__global__ __launch_bounds__(256, MINB) void gemm_k(
    const bf16* __restrict__ a0h, const bf16* __restrict__ a0l,
    const bf16* __restrict__ a1h, const bf16* __restrict__ a1l,
    const bf16* __restrict__ a2h, const bf16* __restrict__ a2l,
    const bf16* __restrict__ a3h, const bf16* __restrict__ a3l,
    const bf16* __restrict__ Bh, const bf16* __restrict__ Bl,
    const float* __restrict__ bias, int K, int N, int relu,
    bf16* __restrict__ Ch, bf16* __restrict__ Cl, float* __restrict__ Cys, int jj,
    float* __restrict__ st_c,
    bf16* __restrict__ hrh, bf16* __restrict__ hrl,
    bf16* __restrict__ hh,  bf16* __restrict__ hl,
    const float* __restrict__ lamp,
    const float* __restrict__ npj, const float* __restrict__ nqj,
    bf16* __restrict__ zh, bf16* __restrict__ zl,
    float* __restrict__ o_mpost, float* __restrict__ o_lvpost,
    float* __restrict__ o_mprior, float* __restrict__ o_lvprior,
    float* __restrict__ o_zpostj, float* __restrict__ o_zpriorj)
{
    extern __shared__ char dsm[];
    const int tid  = threadIdx.x;
    const int wid  = tid >> 5;
    const int lane = tid & 31;
    const int wm   = wid >> 2;
    const int wn   = wid & 3;
    const int row0 = blockIdx.x * 64;
    const int col0 = blockIdx.y * 128;
    const uint32_t sb = s2u(dsm);
    const uint32_t aLane = (uint32_t)(lane & 15) * 80 + ((lane >> 4) << 4);

    float acc[2][NT][4];
#pragma unroll
    for (int m = 0; m < 2; m++)
#pragma unroll
        for (int n = 0; n < NT; n++)
#pragma unroll
            for (int q = 0; q < 4; q++) acc[m][n][q] = 0.f;

    const int NC   = K >> 5;
    const int NBLK = N >> 3;
    const uint2* __restrict__ fgh = (const uint2*)Bh;
    const uint2* __restrict__ fgl = (const uint2*)Bl;

    auto asrc = [&](int cg, int b, const bf16*& ph, const bf16*& pl) {
        if (GSEG == 0) {
            ph = a0h + (size_t)b * K + cg;
            pl = a0l + (size_t)b * K + cg;
        } else if (GSEG == 1) {
            if (cg < 128)      { ph = a0h + (size_t)b * 128 + cg;       pl = a0l + (size_t)b * 128 + cg; }
            else if (cg < 384) { ph = a1h + (size_t)b * 256 + cg - 128; pl = a1l + (size_t)b * 256 + cg - 128; }
            else if (cg < 640) { ph = a2h + (size_t)b * 256 + cg - 384; pl = a2l + (size_t)b * 256 + cg - 384; }
            else               { ph = a3h + (size_t)b * 256 + cg - 640; pl = a3l + (size_t)b * 256 + cg - 640; }
        } else {
            int o = cg & 255;
            if (cg < 256)      { ph = a0h + (size_t)b * 256 + o; pl = a0l + (size_t)b * 256 + o; }
            else if (cg < 512) { ph = a1h + (size_t)b * 256 + o; pl = a1l + (size_t)b * 256 + o; }
            else if (cg < 768) { ph = a2h + (size_t)b * 256 + o; pl = a2l + (size_t)b * 256 + o; }
            else               { ph = a3h + (size_t)b * 256 + o; pl = a3l + (size_t)b * 256 + o; }
        }
    };

    auto issue = [&](int c, uint32_t st) {
        int kt = c << 5;
        int ar = tid >> 2, ac = (tid & 3) * 8;
        const bf16 *ph, *pl;
        asrc(kt + ac, row0 + ar, ph, pl);
        uint32_t d = st + (uint32_t)ar * 80 + (uint32_t)ac * 2;
        cpa(d, ph);
        cpa(d + ASTG, pl);
    };

    issue(0, sb);
    asm volatile("cp.async.commit_group;");
    issue(1, sb + SSZ);
    asm volatile("cp.async.commit_group;");

    uint2 bh[NT], bl[NT];

    for (int c = 0; c < NC; c++) {
        // uint2 index of ks0 half of record (c*NBLK + col0/8 + wn*4 + nt, lane)
        size_t rbase = (((size_t)(c * NBLK + (col0 >> 3) + wn * 4) << 5) + lane) * 2;
#pragma unroll
        for (int nt = 0; nt < NT; nt++) {       // prefetch ks0 halves
            bh[nt] = fgh[rbase + nt * 64];
            bl[nt] = fgl[rbase + nt * 64];
        }

        asm volatile("cp.async.wait_group 1;");
        __syncthreads();
        const uint32_t st = sb + (uint32_t)(c % 3) * SSZ;
        if (c + 2 < NC) issue(c + 2, sb + (uint32_t)((c + 2) % 3) * SSZ);
        asm volatile("cp.async.commit_group;");

        // ---- ks = 0 ----
#pragma unroll
        for (int mt = 0; mt < 2; mt++) {
            uint32_t off = (uint32_t)(wm * 32 + mt * 16) * 80 + aLane;
            uint32_t ah[4], al[4];
            ldm_x4(ah[0], ah[1], ah[2], ah[3], st + off);
            ldm_x4(al[0], al[1], al[2], al[3], st + ASTG + off);
#pragma unroll
            for (int nt = 0; nt < NT; nt++) {
                uint32_t bb[2] = {bh[nt].x, bh[nt].y};
                mma16816(acc[mt][nt], ah, bb);
            }
#pragma unroll
            for (int nt = 0; nt < NT; nt++) {
                uint32_t bb[2] = {bh[nt].x, bh[nt].y};
                mma16816(acc[mt][nt], al, bb);
            }
#pragma unroll
            for (int nt = 0; nt < NT; nt++) {
                uint32_t bb[2] = {bl[nt].x, bl[nt].y};
                mma16816(acc[mt][nt], ah, bb);
            }
        }

        // reload B regs with ks1 halves (same 16B records -> L1 sector hits)
#pragma unroll
        for (int nt = 0; nt < NT; nt++) {
            bh[nt] = fgh[rbase + nt * 64 + 1];
            bl[nt] = fgl[rbase + nt * 64 + 1];
        }

        // ---- ks = 1 ----
#pragma unroll
        for (int mt = 0; mt < 2; mt++) {
            uint32_t off = (uint32_t)(wm * 32 + mt * 16) * 80 + 32 + aLane;
            uint32_t ah[4], al[4];
            ldm_x4(ah[0], ah[1], ah[2], ah[3], st + off);
            ldm_x4(al[0], al[1], al[2], al[3], st + ASTG + off);
#pragma unroll
            for (int nt = 0; nt < NT; nt++) {
                uint32_t bb[2] = {bh[nt].x, bh[nt].y};
                mma16816(acc[mt][nt], ah, bb);
            }
#pragma unroll
            for (int nt = 0; nt < NT; nt++) {
                uint32_t bb[2] = {bh[nt].x, bh[nt].y};
                mma16816(acc[mt][nt], al, bb);
            }
#pragma unroll
            for (int nt = 0; nt < NT; nt++) {
                uint32_t bb[2] = {bl[nt].x, bl[nt].y};
                mma16816(acc[mt][nt], ah, bb);
            }
        }
    }

    // ---- epilogues ----
    if (EPI == 0) {
#pragma unroll
        for (int mt = 0; mt < 2; mt++) {
#pragma unroll
            for (int nt = 0; nt < NT; nt++) {
                int gc = col0 + wn * (NT * 8) + nt * 8 + (lane & 3) * 2;
                float b0 = bias[gc], b1 = bias[gc + 1];
#pragma unroll
                for (int hh2 = 0; hh2 < 2; hh2++) {
                    int gr = row0 + wm * 32 + mt * 16 + (lane >> 2) + hh2 * 8;
                    float v0 = acc[mt][nt][2 * hh2]     + b0;
                    float v1 = acc[mt][nt][2 * hh2 + 1] + b1;
                    if (relu) { v0 = fmaxf(v0, 0.f); v1 = fmaxf(v1, 0.f); }
                    if (WBF) {
                        bf16 h0, l0, h1, l1;
                        split_bf16(v0, h0, l0); split_bf16(v1, h1, l1);
                        *(__nv_bfloat162*)&Ch[(size_t)gr * N + gc] = __nv_bfloat162(h0, h1);
                        *(__nv_bfloat162*)&Cl[(size_t)gr * N + gc] = __nv_bfloat162(l0, l1);
                    }
                    if (WYS)
                        *(float2*)&Cys[((size_t)gr * PP + jj) * N + gc] = make_float2(v0, v1);
                }
            }
        }
    } else if (EPI == 1) {
        // gates, cols n' = 4u+g (g in {i,f,g,o}); lane-pair exchange
#pragma unroll
        for (int mt = 0; mt < 2; mt++) {
#pragma unroll
            for (int nt = 0; nt < NT; nt++) {
                int gc = col0 + wn * (NT * 8) + nt * 8 + (lane & 3) * 2;
                float b0 = bias[gc], b1 = bias[gc + 1];
                int ul = (col0 + wn * (NT * 8) + nt * 8) / 4 + ((lane & 3) >> 1);
#pragma unroll
                for (int hh2 = 0; hh2 < 2; hh2++) {
                    float u0 = acc[mt][nt][2 * hh2]     + b0;
                    float u1 = acc[mt][nt][2 * hh2 + 1] + b1;
                    float x0 = __shfl_xor_sync(0xffffffffu, u0, 1);
                    float x1 = __shfl_xor_sync(0xffffffffu, u1, 1);
                    if ((lane & 1) == 0) {
                        int gr = row0 + wm * 32 + mt * 16 + (lane >> 2) + hh2 * 8;
                        int i = gr * 256 + ul;
                        float cv = sigm(u1) * st_c[i] + sigm(u0) * tanhf(x0);
                        st_c[i] = cv;
                        float hr = sigm(x1) * tanhf(cv);
                        bf16 bh_, bl_;
                        split_bf16(hr, bh_, bl_);
                        hrh[i] = bh_; hrl[i] = bl_;
                        float hv = lamp[jj * BATCH + gr] * hr;
                        split_bf16(hv, bh_, bl_);
                        hh[i] = bh_; hl[i] = bl_;
                    }
                }
            }
        }
    } else {
        // ML, cols n' = 4z+t (t in {mj,lj,mp,lp}); even lane posterior, odd prior
#pragma unroll
        for (int mt = 0; mt < 2; mt++) {
#pragma unroll
            for (int nt = 0; nt < NT; nt++) {
                int gc = col0 + wn * (NT * 8) + nt * 8 + (lane & 3) * 2;
                float b0 = bias[gc], b1 = bias[gc + 1];
                int z = (col0 + wn * (NT * 8) + nt * 8) / 4 + ((lane & 3) >> 1);
#pragma unroll
                for (int hh2 = 0; hh2 < 2; hh2++) {
                    int gr = row0 + wm * 32 + mt * 16 + (lane >> 2) + hh2 * 8;
                    float m = fmaxf(acc[mt][nt][2 * hh2]     + b0, 0.f);
                    float v = fmaxf(acc[mt][nt][2 * hh2 + 1] + b1, 0.f);
                    size_t o1 = ((size_t)gr * PP + jj) * 128 + z;
                    size_t o2 = (size_t)gr * 128 + z;
                    if ((lane & 1) == 0) {
                        o_mpost[o1]  = m;
                        o_lvpost[o1] = v;
                        float zj = m + npj[o2] * expf(0.5f * v);
                        o_zpostj[o2] = zj;
                        bf16 zh_, zl_;
                        split_bf16(zj, zh_, zl_);
                        zh[o2] = zh_; zl[o2] = zl_;
                    } else {
                        o_mprior[o1]  = m;
                        o_lvprior[o1] = v;
                        o_zpriorj[o2] = m + nqj[o2] * expf(0.5f * v);
                    }
                }
            }
        }
    }
}

// ================= setup =================
__global__ void init_state()
{
    int i = blockIdx.x * blockDim.x + threadIdx.x;
    if (i < BATCH * 256) {
        g_c[i] = 0.f;
        g_y_h[i] = __float2bfloat16(0.f); g_y_l[i] = __float2bfloat16(0.f);
        g_h_h[i] = __float2bfloat16(0.f); g_h_l[i] = __float2bfloat16(0.f);
    }
    if (i < BATCH * 128) {
        g_z_h[i] = __float2bfloat16(0.f); g_z_l[i] = __float2bfloat16(0.f);
    }
}

// decode fragment bf16 index i -> (n, k); record = 8 bf16; record = (c*nblk+nb)*32+lane
__device__ __forceinline__ void frag_decode(int i, int nblk, int& n, int& k)
{
    int e    = i & 7;
    int lane = (i >> 3) & 31;
    int rest = i >> 8;
    int nb   = rest % nblk;
    int c    = rest / nblk;
    n = nb * 8 + (lane >> 2);
    k = c * 32 + ((e >> 2) << 4) + (((e >> 1) & 1) << 3) + ((lane & 3) << 1) + (e & 1);
}

__global__ void build_wb(
    const float* __restrict__ h_i,
    const float* __restrict__ W_lstm, const float* __restrict__ U_lstm,
    const float* __restrict__ b_lstm,
    const float* __restrict__ W1, const float* __restrict__ W2, const float* __restrict__ W3,
    const float* __restrict__ W4, const float* __restrict__ W7,
    const float* __restrict__ W5, const float* __restrict__ W6,
    const float* __restrict__ W8, const float* __restrict__ W9,
    const float* __restrict__ b4, const float* __restrict__ b7,
    const float* __restrict__ b5, const float* __restrict__ b6,
    const float* __restrict__ b8, const float* __restrict__ b9)
{
    int i = blockIdx.x * blockDim.x + threadIdx.x;
    if (i < BATCH * 256) split_bf16(h_i[i], g_hi_h[i], g_hi_l[i]);

    if (i < 1024 * 896) {                       // gates frag, gate-interleaved n'=4u+g
        int n, k; frag_decode(i, 128, n, k);
        int u = n >> 2, g = n & 3;
        int col = g * 256 + u;
        float v = (k < 640) ? W_lstm[k * 1024 + col] : U_lstm[(k - 640) * 1024 + col];
        split_bf16(v, g_Wgt_h[i], g_Wgt_l[i]);
    }
    if (i < 256 * 1024) {                       // Wq frag (N=256, K=1024)
        int n, k; frag_decode(i, 32, n, k);
        float v;
        if (n < 128) v = W4[k * 128 + n];
        else {
            int cc = n - 128;
            if (k < 512)      v = W7[k * 128 + cc];
            else if (k < 768) v = 0.f;
            else              v = W7[(k - 256) * 128 + cc];
        }
        split_bf16(v, g_Wqt_h[i], g_Wqt_l[i]);
    }
    if (i < 512 * 256) {                        // Wml frag (N=512, K=256), n'=4z+t
        int n, k; frag_decode(i, 64, n, k);
        int z = n >> 2, t = n & 3;
        float v = 0.f;
        if (t < 2) { if (k < 128)  v = (t == 0 ? W5 : W6)[k * 128 + z]; }
        else       { if (k >= 128) v = (t == 2 ? W8 : W9)[(k - 128) * 128 + z]; }
        split_bf16(v, g_Wmlt_h[i], g_Wmlt_l[i]);
    }
    if (i < 256 * 256) {                        // W1/2/3 frag (N=256, K=256)
        int n, k; frag_decode(i, 32, n, k);
        split_bf16(W1[k * 256 + n], g_W1t_h[i], g_W1t_l[i]);
        split_bf16(W2[k * 256 + n], g_W2t_h[i], g_W2t_l[i]);
        split_bf16(W3[k * 256 + n], g_W3t_h[i], g_W3t_l[i]);
    }
    if (i < 1024) g_bg[i] = b_lstm[(i & 3) * 256 + (i >> 2)];
    if (i < 256)  g_bq[i] = (i < 128) ? b4[i] : b7[i - 128];
    if (i < 512) {
        int z = i >> 2, t = i & 3;
        g_bml[i] = (t == 0) ? b5[z] : (t == 1) ? b6[z] : (t == 2) ? b8[z] : b9[z];
    }
}

__global__ void time_feat(const float* __restrict__ t,
                          const float* __restrict__ alpha,
                          const float* __restrict__ beta,
                          const float* __restrict__ base,
                          float* __restrict__ out_prob)
{
    int b = blockIdx.x * blockDim.x + threadIdx.x;
    if (b >= BATCH) return;
    float al = *alpha, be = *beta, ba = *base;
    float tv[TT];
#pragma unroll
    for (int i = 0; i < TT; i++) tv[i] = t[b * TT + i];
#pragma unroll
    for (int j = 0; j < PP; j++) {
        int cti = PREV_ + j;
        float ct = tv[cti], last = tv[cti - 1];
        float tk = 0.f, td = 0.f;
        for (int i = 0; i < cti; i++) {
            tk += expf(be * (tv[i] - ct));
            td += expf(be * (tv[i] - last));
        }
        float lm = ba + al * tk;
        g_lam[j * BATCH + b] = lm;
        out_prob[j * BATCH + b] = lm * expf((last - ct) * ba + (al / be) * (tk - td));
    }
}

// ================= host launch =================
template<typename T>
static T* sym(const void* s) { void* p; cudaGetSymbolAddress(&p, s); return (T*)p; }

extern "C" void kernel_launch(void* const* d_in, const int* in_sizes, int n_in,
                              void* d_out, int out_size)
{
    (void)in_sizes; (void)n_in; (void)out_size;
    const float* h_i    = (const float*)d_in[0];
    const float* inpt   = (const float*)d_in[1];
    const float* npost  = (const float*)d_in[2];
    const float* nprior = (const float*)d_in[3];
    const float* W_lstm = (const float*)d_in[4];
    const float* U_lstm = (const float*)d_in[5];
    const float* b_lstm = (const float*)d_in[6];
    const float* W1 = (const float*)d_in[7];  const float* b1 = (const float*)d_in[8];
    const float* W2 = (const float*)d_in[9];  const float* b2 = (const float*)d_in[10];
    const float* W3 = (const float*)d_in[11]; const float* b3 = (const float*)d_in[12];
    const float* W4 = (const float*)d_in[13]; const float* b4 = (const float*)d_in[14];
    const float* W5 = (const float*)d_in[15]; const float* b5 = (const float*)d_in[16];
    const float* W6 = (const float*)d_in[17]; const float* b6 = (const float*)d_in[18];
    const float* W7 = (const float*)d_in[19]; const float* b7 = (const float*)d_in[20];
    const float* W8 = (const float*)d_in[21]; const float* b8 = (const float*)d_in[22];
    const float* W9 = (const float*)d_in[23]; const float* b9 = (const float*)d_in[24];
    const float* alpha = (const float*)d_in[25];
    const float* beta  = (const float*)d_in[26];
    const float* base  = (const float*)d_in[27];

    float* out = (float*)d_out;
    float* out_ys      = out;
    float* out_mpost   = out_ys + (size_t)BATCH * PP * 256;
    float* out_lvpost  = out_mpost  + (size_t)BATCH * PP * 128;
    float* out_mprior  = out_lvpost + (size_t)BATCH * PP * 128;
    float* out_lvprior = out_mprior + (size_t)BATCH * PP * 128;
    float* out_zpost   = out_lvprior + (size_t)BATCH * PP * 128;
    float* out_zprior  = out_zpost + (size_t)PP * BATCH * 128;
    float* out_prob    = out_zprior + (size_t)PP * BATCH * 128;

    float* p_c   = sym<float>(g_c);
    float* p_lam = sym<float>(g_lam);
    float* p_bg  = sym<float>(g_bg);
    float* p_bq  = sym<float>(g_bq);
    float* p_bml = sym<float>(g_bml);
    bf16* p_hih = sym<bf16>(g_hi_h);   bf16* p_hil = sym<bf16>(g_hi_l);
    bf16* p_zh  = sym<bf16>(g_z_h);    bf16* p_zl  = sym<bf16>(g_z_l);
    bf16* p_yh  = sym<bf16>(g_y_h);    bf16* p_yl  = sym<bf16>(g_y_l);
    bf16* p_hh  = sym<bf16>(g_h_h);    bf16* p_hl  = sym<bf16>(g_h_l);
    bf16* p_hrh = sym<bf16>(g_hraw_h); bf16* p_hrl = sym<bf16>(g_hraw_l);
    bf16* p_y1h = sym<bf16>(g_y1_h);   bf16* p_y1l = sym<bf16>(g_y1_l);
    bf16* p_y2h = sym<bf16>(g_y2_h);   bf16* p_y2l = sym<bf16>(g_y2_l);
    bf16* p_HZh = sym<bf16>(g_HZ_h);   bf16* p_HZl = sym<bf16>(g_HZ_l);
    bf16* p_Wgh = sym<bf16>(g_Wgt_h);  bf16* p_Wgl = sym<bf16>(g_Wgt_l);
    bf16* p_W1h = sym<bf16>(g_W1t_h);  bf16* p_W1l = sym<bf16>(g_W1t_l);
    bf16* p_W2h = sym<bf16>(g_W2t_h);  bf16* p_W2l = sym<bf16>(g_W2t_l);
    bf16* p_W3h = sym<bf16>(g_W3t_h);  bf16* p_W3l = sym<bf16>(g_W3t_l);
    bf16* p_Wqh = sym<bf16>(g_Wqt_h);  bf16* p_Wql = sym<bf16>(g_Wqt_l);
    bf16* p_Wmh = sym<bf16>(g_Wmlt_h); bf16* p_Wml = sym<bf16>(g_Wmlt_l);

    auto* kGate = gemm_k<1, 1, 0, 0, 3>;
    auto* kY    = gemm_k<0, 0, 1, 0, 2>;
    auto* kY3   = gemm_k<0, 0, 1, 1, 2>;
    auto* kXQ   = gemm_k<2, 0, 1, 0, 2>;
    auto* kML   = gemm_k<0, 2, 0, 0, 2>;
    cudaFuncSetAttribute(kGate, cudaFuncAttributeMaxDynamicSharedMemorySize, SMTOT);
    cudaFuncSetAttribute(kY,    cudaFuncAttributeMaxDynamicSharedMemorySize, SMTOT);
    cudaFuncSetAttribute(kY3,   cudaFuncAttributeMaxDynamicSharedMemorySize, SMTOT);
    cudaFuncSetAttribute(kXQ,   cudaFuncAttributeMaxDynamicSharedMemorySize, SMTOT);
    cudaFuncSetAttribute(kML,   cudaFuncAttributeMaxDynamicSharedMemorySize, SMTOT);

    const int TPB = 256;
    init_state<<<(BATCH * 256 + TPB - 1) / TPB, TPB>>>();
    build_wb<<<(BATCH * 256 + TPB - 1) / TPB, TPB>>>(
        h_i, W_lstm, U_lstm, b_lstm, W1, W2, W3, W4, W7, W5, W6, W8, W9,
        b4, b7, b5, b6, b8, b9);
    time_feat<<<(BATCH + TPB - 1) / TPB, TPB>>>(inpt, alpha, beta, base, out_prob);

    for (int j = 0; j < PP; j++) {
        int rd = j & 1, wr = 1 - rd;
        bf16* zrh = p_zh + (size_t)rd * BATCH * 128;
        bf16* zrl = p_zl + (size_t)rd * BATCH * 128;
        bf16* zwh = p_zh + (size_t)wr * BATCH * 128;
        bf16* zwl = p_zl + (size_t)wr * BATCH * 128;
        bf16* yrh = p_yh + (size_t)rd * BATCH * 256;
        bf16* yrl = p_yl + (size_t)rd * BATCH * 256;
        bf16* ywh = p_yh + (size_t)wr * BATCH * 256;
        bf16* ywl = p_yl + (size_t)wr * BATCH * 256;
        bf16* hrdh = p_hh + (size_t)rd * BATCH * 256;
        bf16* hrdl = p_hl + (size_t)rd * BATCH * 256;
        bf16* hwrh = p_hh + (size_t)wr * BATCH * 256;
        bf16* hwrl = p_hl + (size_t)wr * BATCH * 256;

        kGate<<<dim3(64, 8), 256, SMTOT>>>(
            zrh, zrl, p_hih, p_hil, yrh, yrl, hrdh, hrdl,
            p_Wgh, p_Wgl, p_bg, 896, 1024, 0,
            nullptr, nullptr, nullptr, j,
            p_c, p_hrh, p_hrl, hwrh, hwrl, p_lam,
            nullptr, nullptr, nullptr, nullptr,
            nullptr, nullptr, nullptr, nullptr, nullptr, nullptr);

        kY<<<dim3(64, 2), 256, SMTOT>>>(
            p_hrh, p_hrl, nullptr, nullptr, nullptr, nullptr, nullptr, nullptr,
            p_W1h, p_W1l, b1, 256, 256, 1,
            p_y1h, p_y1l, nullptr, 0,
            nullptr, nullptr, nullptr, nullptr, nullptr, nullptr,
            nullptr, nullptr, nullptr, nullptr,
            nullptr, nullptr, nullptr, nullptr, nullptr, nullptr);
        kY<<<dim3(64, 2), 256, SMTOT>>>(
            p_y1h, p_y1l, nullptr, nullptr, nullptr, nullptr, nullptr, nullptr,
            p_W2h, p_W2l, b2, 256, 256, 1,
            p_y2h, p_y2l, nullptr, 0,
            nullptr, nullptr, nullptr, nullptr, nullptr, nullptr,
            nullptr, nullptr, nullptr, nullptr,
            nullptr, nullptr, nullptr, nullptr, nullptr, nullptr);
        kY3<<<dim3(64, 2), 256, SMTOT>>>(
            p_y2h, p_y2l, nullptr, nullptr, nullptr, nullptr, nullptr, nullptr,
            p_W3h, p_W3l, b3, 256, 256, 1,
            ywh, ywl, out_ys, j,
            nullptr, nullptr, nullptr, nullptr, nullptr, nullptr,
            nullptr, nullptr, nullptr, nullptr,
            nullptr, nullptr, nullptr, nullptr, nullptr, nullptr);

        kXQ<<<dim3(64, 2), 256, SMTOT>>>(
            p_hih, p_hil, p_hrh, p_hrl, ywh, ywl, yrh, yrl,
            p_Wqh, p_Wql, p_bq, 1024, 256, 1,
            p_HZh, p_HZl, nullptr, 0,
            nullptr, nullptr, nullptr, nullptr, nullptr, nullptr,
            nullptr, nullptr, nullptr, nullptr,
            nullptr, nullptr, nullptr, nullptr, nullptr, nullptr);

        kML<<<dim3(64, 4), 256, SMTOT>>>(
            p_HZh, p_HZl, nullptr, nullptr, nullptr, nullptr, nullptr, nullptr,
            p_Wmh, p_Wml, p_bml, 256, 512, 1,
            nullptr, nullptr, nullptr, j,
            nullptr, nullptr, nullptr, nullptr, nullptr, nullptr,
            npost + (size_t)j * BATCH * 128, nprior + (size_t)j * BATCH * 128,
            zwh, zwl,
            out_mpost, out_lvpost, out_mprior, out_lvprior,
            out_zpost + (size_t)j * BATCH * 128, out_zprior + (size_t)j * BATCH * 128);
    }
}

// round 15
// speedup vs baseline: 1.0855x; 1.0855x over previous
#include <cuda_runtime.h>
#include <cuda_bf16.h>
#include <math.h>
#include <stdint.h>

#define BATCH 4096
#define TT    16
#define PP    10
#define PREV_ 5
typedef __nv_bfloat16 bf16;

// ================= device scratch =================
__device__ float g_c[BATCH * 256];
__device__ float g_lam[PP * BATCH];
__device__ float g_bg[1024];
__device__ float g_bq[256];
__device__ float g_bml[512];
__device__ int   g_flags[4 * 64];              // per-(stage,rowblock) counters
__device__ bf16 g_hi_h[BATCH * 256],   g_hi_l[BATCH * 256];
__device__ bf16 g_z_h[2 * BATCH * 128], g_z_l[2 * BATCH * 128];
__device__ bf16 g_y_h[2 * BATCH * 256], g_y_l[2 * BATCH * 256];
__device__ bf16 g_h_h[2 * BATCH * 256], g_h_l[2 * BATCH * 256];
__device__ bf16 g_hraw_h[BATCH * 256], g_hraw_l[BATCH * 256];
__device__ bf16 g_y1_h[BATCH * 256],   g_y1_l[BATCH * 256];
__device__ bf16 g_y2_h[BATCH * 256],   g_y2_l[BATCH * 256];
__device__ bf16 g_HZ_h[BATCH * 256],   g_HZ_l[BATCH * 256];
// fragment-major weights (PTX m16n8k16 B-fragment layout, ks0/ks1 packed per 16B)
__device__ bf16 g_Wgt_h[1024 * 896],  g_Wgt_l[1024 * 896];   // gate-interleaved
__device__ bf16 g_W1t_h[256 * 256],   g_W1t_l[256 * 256];
__device__ bf16 g_W2t_h[256 * 256],   g_W2t_l[256 * 256];
__device__ bf16 g_W3t_h[256 * 256],   g_W3t_l[256 * 256];
__device__ bf16 g_Wqt_h[256 * 1024],  g_Wqt_l[256 * 1024];
__device__ bf16 g_Wmlt_h[512 * 256],  g_Wmlt_l[512 * 256];   // stat-interleaved

__device__ __forceinline__ void split_bf16(float x, bf16& h, bf16& l) {
    h = __float2bfloat16(x);
    l = __float2bfloat16(x - __bfloat162float(h));
}
__device__ __forceinline__ uint32_t s2u(const void* p) {
    uint32_t r;
    asm("{ .reg .u64 t; cvta.to.shared.u64 t, %1; cvt.u32.u64 %0, t; }"
        : "=r"(r) : "l"(p));
    return r;
}
__device__ __forceinline__ void cpa(uint32_t d, const void* s) {
    asm volatile("cp.async.cg.shared.global [%0], [%1], 16;" :: "r"(d), "l"(s));
}
__device__ __forceinline__ void ldm_x4(uint32_t& r0, uint32_t& r1,
                                       uint32_t& r2, uint32_t& r3, uint32_t a) {
    asm volatile("ldmatrix.sync.aligned.m8n8.x4.shared.b16 {%0,%1,%2,%3}, [%4];"
                 : "=r"(r0), "=r"(r1), "=r"(r2), "=r"(r3) : "r"(a));
}
__device__ __forceinline__ void mma16816(float* c, const uint32_t* a,
                                         const uint32_t* b) {
    asm volatile(
        "mma.sync.aligned.m16n8k16.row.col.f32.bf16.bf16.f32 "
        "{%0,%1,%2,%3}, {%4,%5,%6,%7}, {%8,%9}, {%0,%1,%2,%3};"
        : "+f"(c[0]), "+f"(c[1]), "+f"(c[2]), "+f"(c[3])
        : "r"(a[0]), "r"(a[1]), "r"(a[2]), "r"(a[3]), "r"(b[0]), "r"(b[1]));
}
__device__ __forceinline__ float sigm(float x) { return 1.f / (1.f + expf(-x)); }

#define NT   4
#define ASTG (64 * 80)             // 5120, one A array (h or l)
#define SSZ  (2 * ASTG)            // 10240 per stage
#define SMTOT (3 * SSZ)            // 30720

// ---- inter-block row flags ----
__device__ __forceinline__ void flag_bump(int* f) {
    __threadfence();
    __syncthreads();
    if (threadIdx.x == 0) atomicAdd(f, 1);
}
__device__ __forceinline__ void flag_wait(int* f, int tgt) {
    if (threadIdx.x == 0) {
        int v;
        do { asm volatile("ld.acquire.gpu.b32 %0, [%1];" : "=r"(v) : "l"(f)); }
        while (v < tgt);
    }
    __syncthreads();
}

// ================= GEMM core: A via cp.async smem, B via uint4 fragment LDG ===
// BM=64, BN=128, BK=32, 3-stage. acc zeroed inside.
// GSEG: 0 single A src (stride K); 2 xq gather {256 x4}.
template<int GSEG>
__device__ __forceinline__ void gemm_core(
    const bf16* __restrict__ a0h, const bf16* __restrict__ a0l,
    const bf16* __restrict__ a1h, const bf16* __restrict__ a1l,
    const bf16* __restrict__ a2h, const bf16* __restrict__ a2l,
    const bf16* __restrict__ a3h, const bf16* __restrict__ a3l,
    const uint4* __restrict__ fgh, const uint4* __restrict__ fgl,
    int K, int NBLK, int row0, int col0, uint32_t sb,
    float acc[2][NT][4])
{
    const int tid  = threadIdx.x;
    const int lane = tid & 31;
    const int wid  = tid >> 5;
    const int wm   = wid >> 2;
    const int wn   = wid & 3;
    const uint32_t aLane = (uint32_t)(lane & 15) * 80 + ((lane >> 4) << 4);

#pragma unroll
    for (int m = 0; m < 2; m++)
#pragma unroll
        for (int n = 0; n < NT; n++)
#pragma unroll
            for (int q = 0; q < 4; q++) acc[m][n][q] = 0.f;

    const int NC = K >> 5;

    auto asrc = [&](int cg, int b, const bf16*& ph, const bf16*& pl) {
        if (GSEG == 0) {
            ph = a0h + (size_t)b * K + cg;
            pl = a0l + (size_t)b * K + cg;
        } else {
            int o = cg & 255;
            if (cg < 256)      { ph = a0h + (size_t)b * 256 + o; pl = a0l + (size_t)b * 256 + o; }
            else if (cg < 512) { ph = a1h + (size_t)b * 256 + o; pl = a1l + (size_t)b * 256 + o; }
            else if (cg < 768) { ph = a2h + (size_t)b * 256 + o; pl = a2l + (size_t)b * 256 + o; }
            else               { ph = a3h + (size_t)b * 256 + o; pl = a3l + (size_t)b * 256 + o; }
        }
    };
    auto issue = [&](int c, uint32_t st) {
        int kt = c << 5;
        int ar = tid >> 2, ac = (tid & 3) * 8;
        const bf16 *ph, *pl;
        asrc(kt + ac, row0 + ar, ph, pl);
        uint32_t d = st + (uint32_t)ar * 80 + (uint32_t)ac * 2;
        cpa(d, ph);
        cpa(d + ASTG, pl);
    };

    __syncthreads();                  // smem reuse guard across calls
    issue(0, sb);
    asm volatile("cp.async.commit_group;");
    issue(1, sb + SSZ);
    asm volatile("cp.async.commit_group;");

    for (int c = 0; c < NC; c++) {
        uint4 vh[NT], vl[NT];
        {
            size_t bidx = ((size_t)(c * NBLK + (col0 >> 3) + wn * 4) << 5) + lane;
#pragma unroll
            for (int nt = 0; nt < NT; nt++) {
                vh[nt] = fgh[bidx + nt * 32];
                vl[nt] = fgl[bidx + nt * 32];
            }
        }
        asm volatile("cp.async.wait_group 1;");
        __syncthreads();
        const uint32_t st = sb + (uint32_t)(c % 3) * SSZ;
        if (c + 2 < NC) issue(c + 2, sb + (uint32_t)((c + 2) % 3) * SSZ);
        asm volatile("cp.async.commit_group;");

#pragma unroll
        for (int ks = 0; ks < 2; ks++) {
#pragma unroll
            for (int mt = 0; mt < 2; mt++) {
                uint32_t off = (uint32_t)(wm * 32 + mt * 16) * 80 + ks * 32 + aLane;
                uint32_t ah[4], al[4];
                ldm_x4(ah[0], ah[1], ah[2], ah[3], st + off);
                ldm_x4(al[0], al[1], al[2], al[3], st + ASTG + off);
#pragma unroll
                for (int nt = 0; nt < NT; nt++) {
                    uint32_t bb[2] = {ks ? vh[nt].z : vh[nt].x,
                                      ks ? vh[nt].w : vh[nt].y};
                    mma16816(acc[mt][nt], ah, bb);
                }
#pragma unroll
                for (int nt = 0; nt < NT; nt++) {
                    uint32_t bb[2] = {ks ? vh[nt].z : vh[nt].x,
                                      ks ? vh[nt].w : vh[nt].y};
                    mma16816(acc[mt][nt], al, bb);
                }
#pragma unroll
                for (int nt = 0; nt < NT; nt++) {
                    uint32_t bb[2] = {ks ? vl[nt].z : vl[nt].x,
                                      ks ? vl[nt].w : vl[nt].y};
                    mma16816(acc[mt][nt], ah, bb);
                }
            }
        }
    }
    asm volatile("cp.async.wait_group 0;");
}

// ---- epilogues ----
__device__ __forceinline__ void epi_bf(
    float acc[2][NT][4], const float* __restrict__ bias,
    bf16* __restrict__ Ch, bf16* __restrict__ Cl,
    float* __restrict__ Cys, int jj, int N, int row0, int col0)
{
    const int lane = threadIdx.x & 31;
    const int wid  = threadIdx.x >> 5;
    const int wm = wid >> 2, wn = wid & 3;
#pragma unroll
    for (int mt = 0; mt < 2; mt++) {
#pragma unroll
        for (int nt = 0; nt < NT; nt++) {
            int gc = col0 + wn * 32 + nt * 8 + (lane & 3) * 2;
            float b0 = bias[gc], b1 = bias[gc + 1];
#pragma unroll
            for (int hh2 = 0; hh2 < 2; hh2++) {
                int gr = row0 + wm * 32 + mt * 16 + (lane >> 2) + hh2 * 8;
                float v0 = fmaxf(acc[mt][nt][2 * hh2]     + b0, 0.f);
                float v1 = fmaxf(acc[mt][nt][2 * hh2 + 1] + b1, 0.f);
                bf16 h0, l0, h1, l1;
                split_bf16(v0, h0, l0); split_bf16(v1, h1, l1);
                *(__nv_bfloat162*)&Ch[(size_t)gr * N + gc] = __nv_bfloat162(h0, h1);
                *(__nv_bfloat162*)&Cl[(size_t)gr * N + gc] = __nv_bfloat162(l0, l1);
                if (Cys)
                    *(float2*)&Cys[((size_t)gr * PP + jj) * N + gc] = make_float2(v0, v1);
            }
        }
    }
}

__device__ __forceinline__ void epi_sample(
    float acc[2][NT][4], const float* __restrict__ bias,
    int jj, int row0, int col0,
    const float* __restrict__ npj, const float* __restrict__ nqj,
    bf16* __restrict__ zh, bf16* __restrict__ zl,
    float* __restrict__ o_mpost, float* __restrict__ o_lvpost,
    float* __restrict__ o_mprior, float* __restrict__ o_lvprior,
    float* __restrict__ o_zpostj, float* __restrict__ o_zpriorj)
{
    const int lane = threadIdx.x & 31;
    const int wid  = threadIdx.x >> 5;
    const int wm = wid >> 2, wn = wid & 3;
#pragma unroll
    for (int mt = 0; mt < 2; mt++) {
#pragma unroll
        for (int nt = 0; nt < NT; nt++) {
            int gc = col0 + wn * 32 + nt * 8 + (lane & 3) * 2;
            float b0 = bias[gc], b1 = bias[gc + 1];
            int z = (col0 + wn * 32 + nt * 8) / 4 + ((lane & 3) >> 1);
#pragma unroll
            for (int hh2 = 0; hh2 < 2; hh2++) {
                int gr = row0 + wm * 32 + mt * 16 + (lane >> 2) + hh2 * 8;
                float m = fmaxf(acc[mt][nt][2 * hh2]     + b0, 0.f);
                float v = fmaxf(acc[mt][nt][2 * hh2 + 1] + b1, 0.f);
                size_t o1 = ((size_t)gr * PP + jj) * 128 + z;
                size_t o2 = (size_t)gr * 128 + z;
                if ((lane & 1) == 0) {
                    o_mpost[o1]  = m;
                    o_lvpost[o1] = v;
                    float zj = m + npj[o2] * expf(0.5f * v);
                    o_zpostj[o2] = zj;
                    bf16 zh_, zl_;
                    split_bf16(zj, zh_, zl_);
                    zh[o2] = zh_; zl[o2] = zl_;
                } else {
                    o_mprior[o1]  = m;
                    o_lvprior[o1] = v;
                    o_zpriorj[o2] = m + nqj[o2] * expf(0.5f * v);
                }
            }
        }
    }
}

// ================= gates GEMM (R12 winner) + fused LSTM epilogue =================
__global__ __launch_bounds__(256, 2) void gates_k(
    const bf16* __restrict__ zrh, const bf16* __restrict__ zrl,
    const bf16* __restrict__ hih, const bf16* __restrict__ hil,
    const bf16* __restrict__ yrh, const bf16* __restrict__ yrl,
    const bf16* __restrict__ hdh, const bf16* __restrict__ hdl,
    const bf16* __restrict__ Bh, const bf16* __restrict__ Bl,
    const float* __restrict__ bias, int jj,
    float* __restrict__ st_c,
    bf16* __restrict__ hrh, bf16* __restrict__ hrl,
    bf16* __restrict__ hh,  bf16* __restrict__ hl,
    const float* __restrict__ lamp)
{
    extern __shared__ char dsm[];
    const int tid  = threadIdx.x;
    const int wid  = tid >> 5;
    const int lane = tid & 31;
    const int wm   = wid >> 2;
    const int wn   = wid & 3;
    const int row0 = blockIdx.x * 64;
    const int col0 = blockIdx.y * 128;
    const uint32_t sb = s2u(dsm);
    const uint32_t aLane = (uint32_t)(lane & 15) * 80 + ((lane >> 4) << 4);
    const int K = 896, NBLK = 128, NC = 28;
    const uint4* __restrict__ fgh = (const uint4*)Bh;
    const uint4* __restrict__ fgl = (const uint4*)Bl;

    float acc[2][NT][4];
#pragma unroll
    for (int m = 0; m < 2; m++)
#pragma unroll
        for (int n = 0; n < NT; n++)
#pragma unroll
            for (int q = 0; q < 4; q++) acc[m][n][q] = 0.f;

    auto asrc = [&](int cg, int b, const bf16*& ph, const bf16*& pl) {
        if (cg < 128)      { ph = zrh + (size_t)b * 128 + cg;       pl = zrl + (size_t)b * 128 + cg; }
        else if (cg < 384) { ph = hih + (size_t)b * 256 + cg - 128; pl = hil + (size_t)b * 256 + cg - 128; }
        else if (cg < 640) { ph = yrh + (size_t)b * 256 + cg - 384; pl = yrl + (size_t)b * 256 + cg - 384; }
        else               { ph = hdh + (size_t)b * 256 + cg - 640; pl = hdl + (size_t)b * 256 + cg - 640; }
    };
    auto issue = [&](int c, uint32_t st) {
        int kt = c << 5;
        int ar = tid >> 2, ac = (tid & 3) * 8;
        const bf16 *ph, *pl;
        asrc(kt + ac, row0 + ar, ph, pl);
        uint32_t d = st + (uint32_t)ar * 80 + (uint32_t)ac * 2;
        cpa(d, ph);
        cpa(d + ASTG, pl);
    };

    issue(0, sb);
    asm volatile("cp.async.commit_group;");
    issue(1, sb + SSZ);
    asm volatile("cp.async.commit_group;");

    for (int c = 0; c < NC; c++) {
        uint4 vh[NT], vl[NT];
        {
            size_t bidx = ((size_t)(c * NBLK + (col0 >> 3) + wn * 4) << 5) + lane;
#pragma unroll
            for (int nt = 0; nt < NT; nt++) {
                vh[nt] = fgh[bidx + nt * 32];
                vl[nt] = fgl[bidx + nt * 32];
            }
        }
        asm volatile("cp.async.wait_group 1;");
        __syncthreads();
        const uint32_t st = sb + (uint32_t)(c % 3) * SSZ;
        if (c + 2 < NC) issue(c + 2, sb + (uint32_t)((c + 2) % 3) * SSZ);
        asm volatile("cp.async.commit_group;");

#pragma unroll
        for (int ks = 0; ks < 2; ks++) {
#pragma unroll
            for (int mt = 0; mt < 2; mt++) {
                uint32_t off = (uint32_t)(wm * 32 + mt * 16) * 80 + ks * 32 + aLane;
                uint32_t ah[4], al[4];
                ldm_x4(ah[0], ah[1], ah[2], ah[3], st + off);
                ldm_x4(al[0], al[1], al[2], al[3], st + ASTG + off);
#pragma unroll
                for (int nt = 0; nt < NT; nt++) {
                    uint32_t bb[2] = {ks ? vh[nt].z : vh[nt].x,
                                      ks ? vh[nt].w : vh[nt].y};
                    mma16816(acc[mt][nt], ah, bb);
                }
#pragma unroll
                for (int nt = 0; nt < NT; nt++) {
                    uint32_t bb[2] = {ks ? vh[nt].z : vh[nt].x,
                                      ks ? vh[nt].w : vh[nt].y};
                    mma16816(acc[mt][nt], al, bb);
                }
#pragma unroll
                for (int nt = 0; nt < NT; nt++) {
                    uint32_t bb[2] = {ks ? vl[nt].z : vl[nt].x,
                                      ks ? vl[nt].w : vl[nt].y};
                    mma16816(acc[mt][nt], ah, bb);
                }
            }
        }
    }

    // fused LSTM epilogue: cols n' = 4u+g
#pragma unroll
    for (int mt = 0; mt < 2; mt++) {
#pragma unroll
        for (int nt = 0; nt < NT; nt++) {
            int gc = col0 + wn * 32 + nt * 8 + (lane & 3) * 2;
            float b0 = bias[gc], b1 = bias[gc + 1];
            int ul = (col0 + wn * 32 + nt * 8) / 4 + ((lane & 3) >> 1);
#pragma unroll
            for (int hh2 = 0; hh2 < 2; hh2++) {
                float u0 = acc[mt][nt][2 * hh2]     + b0;
                float u1 = acc[mt][nt][2 * hh2 + 1] + b1;
                float x0 = __shfl_xor_sync(0xffffffffu, u0, 1);
                float x1 = __shfl_xor_sync(0xffffffffu, u1, 1);
                if ((lane & 1) == 0) {
                    int gr = row0 + wm * 32 + mt * 16 + (lane >> 2) + hh2 * 8;
                    int i = gr * 256 + ul;
                    float cv = sigm(u1) * st_c[i] + sigm(u0) * tanhf(x0);
                    st_c[i] = cv;
                    float hr = sigm(x1) * tanhf(cv);
                    bf16 bh_, bl_;
                    split_bf16(hr, bh_, bl_);
                    hrh[i] = bh_; hrl[i] = bl_;
                    float hv = lamp[jj * BATCH + gr] * hr;
                    split_bf16(hv, bh_, bl_);
                    hh[i] = bh_; hl[i] = bl_;
                }
            }
        }
    }
}

// ================= fused small-GEMM chain: y1->y2->y3->XQ->ML =================
__global__ __launch_bounds__(256, 2) void chain_k(
    const bf16* __restrict__ hih, const bf16* __restrict__ hil,
    const bf16* __restrict__ yrh, const bf16* __restrict__ yrl,
    bf16* __restrict__ ywh, bf16* __restrict__ ywl,
    const float* __restrict__ b1, const float* __restrict__ b2,
    const float* __restrict__ b3,
    float* __restrict__ out_ys, int jj,
    const float* __restrict__ npj, const float* __restrict__ nqj,
    bf16* __restrict__ zwh, bf16* __restrict__ zwl,
    float* __restrict__ o_mpost, float* __restrict__ o_lvpost,
    float* __restrict__ o_mprior, float* __restrict__ o_lvprior,
    float* __restrict__ o_zpostj, float* __restrict__ o_zpriorj)
{
    extern __shared__ char dsm[];
    const uint32_t sb = s2u(dsm);
    const int rb = blockIdx.x;
    const int row0 = rb * 64;
    const int col0 = blockIdx.y * 128;
    const int tgt = 2 * (jj + 1);
    float acc[2][NT][4];

    // stage 1: y1 = relu(hraw @ W1 + b1)
    gemm_core<0>(g_hraw_h, g_hraw_l, nullptr, nullptr, nullptr, nullptr, nullptr, nullptr,
                 (const uint4*)g_W1t_h, (const uint4*)g_W1t_l,
                 256, 32, row0, col0, sb, acc);
    epi_bf(acc, b1, g_y1_h, g_y1_l, nullptr, 0, 256, row0, col0);
    flag_bump(&g_flags[0 * 64 + rb]);

    // stage 2: y2 = relu(y1 @ W2 + b2)
    flag_wait(&g_flags[0 * 64 + rb], tgt);
    gemm_core<0>(g_y1_h, g_y1_l, nullptr, nullptr, nullptr, nullptr, nullptr, nullptr,
                 (const uint4*)g_W2t_h, (const uint4*)g_W2t_l,
                 256, 32, row0, col0, sb, acc);
    epi_bf(acc, b2, g_y2_h, g_y2_l, nullptr, 0, 256, row0, col0);
    flag_bump(&g_flags[1 * 64 + rb]);

    // stage 3: y3 = relu(y2 @ W3 + b3) -> ycur + out_ys
    flag_wait(&g_flags[1 * 64 + rb], tgt);
    gemm_core<0>(g_y2_h, g_y2_l, nullptr, nullptr, nullptr, nullptr, nullptr, nullptr,
                 (const uint4*)g_W3t_h, (const uint4*)g_W3t_l,
                 256, 32, row0, col0, sb, acc);
    epi_bf(acc, b3, ywh, ywl, out_ys, jj, 256, row0, col0);
    flag_bump(&g_flags[2 * 64 + rb]);

    // stage 4: HZ = relu([hi,hraw,ycur,yprev] @ Wq + bq)
    flag_wait(&g_flags[2 * 64 + rb], tgt);
    gemm_core<2>(hih, hil, g_hraw_h, g_hraw_l, ywh, ywl, yrh, yrl,
                 (const uint4*)g_Wqt_h, (const uint4*)g_Wqt_l,
                 1024, 32, row0, col0, sb, acc);
    epi_bf(acc, g_bq, g_HZ_h, g_HZ_l, nullptr, 0, 256, row0, col0);
    flag_bump(&g_flags[3 * 64 + rb]);

    // stage 5: ML = relu(HZ @ Wml + bml) + fused sampling (two 128-col tiles)
    flag_wait(&g_flags[3 * 64 + rb], tgt);
#pragma unroll
    for (int p = 0; p < 2; p++) {
        int col0m = blockIdx.y * 256 + p * 128;
        gemm_core<0>(g_HZ_h, g_HZ_l, nullptr, nullptr, nullptr, nullptr, nullptr, nullptr,
                     (const uint4*)g_Wmlt_h, (const uint4*)g_Wmlt_l,
                     256, 64, row0, col0m, sb, acc);
        epi_sample(acc, g_bml, jj, row0, col0m, npj, nqj, zwh, zwl,
                   o_mpost, o_lvpost, o_mprior, o_lvprior, o_zpostj, o_zpriorj);
    }
}

// ================= setup =================
__global__ void init_state()
{
    int i = blockIdx.x * blockDim.x + threadIdx.x;
    if (i < BATCH * 256) {
        g_c[i] = 0.f;
        g_y_h[i] = __float2bfloat16(0.f); g_y_l[i] = __float2bfloat16(0.f);
        g_h_h[i] = __float2bfloat16(0.f); g_h_l[i] = __float2bfloat16(0.f);
    }
    if (i < BATCH * 128) {
        g_z_h[i] = __float2bfloat16(0.f); g_z_l[i] = __float2bfloat16(0.f);
    }
    if (i < 4 * 64) g_flags[i] = 0;
}

// decode fragment bf16 index i -> (n, k); record = 8 bf16; record = (c*nblk+nb)*32+lane
__device__ __forceinline__ void frag_decode(int i, int nblk, int& n, int& k)
{
    int e    = i & 7;
    int lane = (i >> 3) & 31;
    int rest = i >> 8;
    int nb   = rest % nblk;
    int c    = rest / nblk;
    n = nb * 8 + (lane >> 2);
    k = c * 32 + ((e >> 2) << 4) + (((e >> 1) & 1) << 3) + ((lane & 3) << 1) + (e & 1);
}

__global__ void build_wb(
    const float* __restrict__ h_i,
    const float* __restrict__ W_lstm, const float* __restrict__ U_lstm,
    const float* __restrict__ b_lstm,
    const float* __restrict__ W1, const float* __restrict__ W2, const float* __restrict__ W3,
    const float* __restrict__ W4, const float* __restrict__ W7,
    const float* __restrict__ W5, const float* __restrict__ W6,
    const float* __restrict__ W8, const float* __restrict__ W9,
    const float* __restrict__ b4, const float* __restrict__ b7,
    const float* __restrict__ b5, const float* __restrict__ b6,
    const float* __restrict__ b8, const float* __restrict__ b9)
{
    int i = blockIdx.x * blockDim.x + threadIdx.x;
    if (i < BATCH * 256) split_bf16(h_i[i], g_hi_h[i], g_hi_l[i]);

    if (i < 1024 * 896) {                       // gates frag, gate-interleaved n'=4u+g
        int n, k; frag_decode(i, 128, n, k);
        int u = n >> 2, g = n & 3;
        int col = g * 256 + u;
        float v = (k < 640) ? W_lstm[k * 1024 + col] : U_lstm[(k - 640) * 1024 + col];
        split_bf16(v, g_Wgt_h[i], g_Wgt_l[i]);
    }
    if (i < 256 * 1024) {                       // Wq frag (N=256, K=1024)
        int n, k; frag_decode(i, 32, n, k);
        float v;
        if (n < 128) v = W4[k * 128 + n];
        else {
            int cc = n - 128;
            if (k < 512)      v = W7[k * 128 + cc];
            else if (k < 768) v = 0.f;
            else              v = W7[(k - 256) * 128 + cc];
        }
        split_bf16(v, g_Wqt_h[i], g_Wqt_l[i]);
    }
    if (i < 512 * 256) {                        // Wml frag (N=512, K=256), n'=4z+t
        int n, k; frag_decode(i, 64, n, k);
        int z = n >> 2, t = n & 3;
        float v = 0.f;
        if (t < 2) { if (k < 128)  v = (t == 0 ? W5 : W6)[k * 128 + z]; }
        else       { if (k >= 128) v = (t == 2 ? W8 : W9)[(k - 128) * 128 + z]; }
        split_bf16(v, g_Wmlt_h[i], g_Wmlt_l[i]);
    }
    if (i < 256 * 256) {                        // W1/2/3 frag (N=256, K=256)
        int n, k; frag_decode(i, 32, n, k);
        split_bf16(W1[k * 256 + n], g_W1t_h[i], g_W1t_l[i]);
        split_bf16(W2[k * 256 + n], g_W2t_h[i], g_W2t_l[i]);
        split_bf16(W3[k * 256 + n], g_W3t_h[i], g_W3t_l[i]);
    }
    if (i < 1024) g_bg[i] = b_lstm[(i & 3) * 256 + (i >> 2)];
    if (i < 256)  g_bq[i] = (i < 128) ? b4[i] : b7[i - 128];
    if (i < 512) {
        int z = i >> 2, t = i & 3;
        g_bml[i] = (t == 0) ? b5[z] : (t == 1) ? b6[z] : (t == 2) ? b8[z] : b9[z];
    }
}

__global__ void time_feat(const float* __restrict__ t,
                          const float* __restrict__ alpha,
                          const float* __restrict__ beta,
                          const float* __restrict__ base,
                          float* __restrict__ out_prob)
{
    int b = blockIdx.x * blockDim.x + threadIdx.x;
    if (b >= BATCH) return;
    float al = *alpha, be = *beta, ba = *base;
    float tv[TT];
#pragma unroll
    for (int i = 0; i < TT; i++) tv[i] = t[b * TT + i];
#pragma unroll
    for (int j = 0; j < PP; j++) {
        int cti = PREV_ + j;
        float ct = tv[cti], last = tv[cti - 1];
        float tk = 0.f, td = 0.f;
        for (int i = 0; i < cti; i++) {
            tk += expf(be * (tv[i] - ct));
            td += expf(be * (tv[i] - last));
        }
        float lm = ba + al * tk;
        g_lam[j * BATCH + b] = lm;
        out_prob[j * BATCH + b] = lm * expf((last - ct) * ba + (al / be) * (tk - td));
    }
}

// ================= host launch =================
template<typename T>
static T* sym(const void* s) { void* p; cudaGetSymbolAddress(&p, s); return (T*)p; }

extern "C" void kernel_launch(void* const* d_in, const int* in_sizes, int n_in,
                              void* d_out, int out_size)
{
    (void)in_sizes; (void)n_in; (void)out_size;
    const float* h_i    = (const float*)d_in[0];
    const float* inpt   = (const float*)d_in[1];
    const float* npost  = (const float*)d_in[2];
    const float* nprior = (const float*)d_in[3];
    const float* W_lstm = (const float*)d_in[4];
    const float* U_lstm = (const float*)d_in[5];
    const float* b_lstm = (const float*)d_in[6];
    const float* W1 = (const float*)d_in[7];  const float* b1 = (const float*)d_in[8];
    const float* W2 = (const float*)d_in[9];  const float* b2 = (const float*)d_in[10];
    const float* W3 = (const float*)d_in[11]; const float* b3 = (const float*)d_in[12];
    const float* W4 = (const float*)d_in[13]; const float* b4 = (const float*)d_in[14];
    const float* W5 = (const float*)d_in[15]; const float* b5 = (const float*)d_in[16];
    const float* W6 = (const float*)d_in[17]; const float* b6 = (const float*)d_in[18];
    const float* W7 = (const float*)d_in[19]; const float* b7 = (const float*)d_in[20];
    const float* W8 = (const float*)d_in[21]; const float* b8 = (const float*)d_in[22];
    const float* W9 = (const float*)d_in[23]; const float* b9 = (const float*)d_in[24];
    const float* alpha = (const float*)d_in[25];
    const float* beta  = (const float*)d_in[26];
    const float* base  = (const float*)d_in[27];

    float* out = (float*)d_out;
    float* out_ys      = out;
    float* out_mpost   = out_ys + (size_t)BATCH * PP * 256;
    float* out_lvpost  = out_mpost  + (size_t)BATCH * PP * 128;
    float* out_mprior  = out_lvpost + (size_t)BATCH * PP * 128;
    float* out_lvprior = out_mprior + (size_t)BATCH * PP * 128;
    float* out_zpost   = out_lvprior + (size_t)BATCH * PP * 128;
    float* out_zprior  = out_zpost + (size_t)PP * BATCH * 128;
    float* out_prob    = out_zprior + (size_t)PP * BATCH * 128;

    float* p_c   = sym<float>(g_c);
    float* p_lam = sym<float>(g_lam);
    float* p_bg  = sym<float>(g_bg);
    bf16* p_hih = sym<bf16>(g_hi_h);   bf16* p_hil = sym<bf16>(g_hi_l);
    bf16* p_zh  = sym<bf16>(g_z_h);    bf16* p_zl  = sym<bf16>(g_z_l);
    bf16* p_yh  = sym<bf16>(g_y_h);    bf16* p_yl  = sym<bf16>(g_y_l);
    bf16* p_hh  = sym<bf16>(g_h_h);    bf16* p_hl  = sym<bf16>(g_h_l);
    bf16* p_hrh = sym<bf16>(g_hraw_h); bf16* p_hrl = sym<bf16>(g_hraw_l);
    bf16* p_Wgh = sym<bf16>(g_Wgt_h);  bf16* p_Wgl = sym<bf16>(g_Wgt_l);

    cudaFuncSetAttribute(gates_k, cudaFuncAttributeMaxDynamicSharedMemorySize, SMTOT);
    cudaFuncSetAttribute(chain_k, cudaFuncAttributeMaxDynamicSharedMemorySize, SMTOT);

    const int TPB = 256;
    init_state<<<(BATCH * 256 + TPB - 1) / TPB, TPB>>>();
    build_wb<<<(BATCH * 256 + TPB - 1) / TPB, TPB>>>(
        h_i, W_lstm, U_lstm, b_lstm, W1, W2, W3, W4, W7, W5, W6, W8, W9,
        b4, b7, b5, b6, b8, b9);
    time_feat<<<(BATCH + TPB - 1) / TPB, TPB>>>(inpt, alpha, beta, base, out_prob);

    for (int j = 0; j < PP; j++) {
        int rd = j & 1, wr = 1 - rd;
        bf16* zrh = p_zh + (size_t)rd * BATCH * 128;
        bf16* zrl = p_zl + (size_t)rd * BATCH * 128;
        bf16* zwh = p_zh + (size_t)wr * BATCH * 128;
        bf16* zwl = p_zl + (size_t)wr * BATCH * 128;
        bf16* yrh = p_yh + (size_t)rd * BATCH * 256;
        bf16* yrl = p_yl + (size_t)rd * BATCH * 256;
        bf16* ywh = p_yh + (size_t)wr * BATCH * 256;
        bf16* ywl = p_yl + (size_t)wr * BATCH * 256;
        bf16* hrdh = p_hh + (size_t)rd * BATCH * 256;
        bf16* hrdl = p_hl + (size_t)rd * BATCH * 256;
        bf16* hwrh = p_hh + (size_t)wr * BATCH * 256;
        bf16* hwrl = p_hl + (size_t)wr * BATCH * 256;

        gates_k<<<dim3(64, 8), 256, SMTOT>>>(
            zrh, zrl, p_hih, p_hil, yrh, yrl, hrdh, hrdl,
            p_Wgh, p_Wgl, p_bg, j,
            p_c, p_hrh, p_hrl, hwrh, hwrl, p_lam);

        chain_k<<<dim3(64, 2), 256, SMTOT>>>(
            p_hih, p_hil, yrh, yrl, ywh, ywl,
            b1, b2, b3, out_ys, j,
            npost + (size_t)j * BATCH * 128, nprior + (size_t)j * BATCH * 128,
            zwh, zwl,
            out_mpost, out_lvpost, out_mprior, out_lvprior,
            out_zpost + (size_t)j * BATCH * 128, out_zprior + (size_t)j * BATCH * 128);
    }
}